// round 10
// baseline (speedup 1.0000x reference)
#include <cuda_runtime.h>
#include <cuda_fp16.h>
#include <math.h>

#define Bc   4
#define Tc   2048
#define Cc   2048
#define Hc   16
#define HKVc 4
#define Dc   128
#define Mrows (Bc*Tc)          // 8192
#define KVC  (HKVc*Dc)         // 512

// ---------------- scratch (device globals; no runtime allocation) -----------
__device__ __half g_xh [(size_t)Mrows*Cc];
__device__ __half g_wqh[(size_t)Cc*Cc];
__device__ __half g_wkh[(size_t)KVC*Cc];
__device__ __half g_wvh[(size_t)KVC*Cc];
__device__ __half g_woh[(size_t)Cc*Cc];
__device__ __half g_qh [(size_t)Mrows*Cc];   // [b,t,h,d] (Wq pre-scaled by 1/sqrt(d))
__device__ __half g_kh [(size_t)Mrows*KVC];  // [b,t,hkv,d]
__device__ __half g_vh [(size_t)Mrows*KVC];
__device__ __half g_aoh[(size_t)Mrows*Cc];   // attention output

// ---------------- helpers -----------------------------------------------------
__device__ __forceinline__ unsigned packh2(float x, float y) {
    __half2 h = __floats2half2_rn(x, y);
    return *reinterpret_cast<unsigned*>(&h);
}

// D(16x8 fp32) += A(16x16 fp16, row) * B(16x8 fp16, col)
__device__ __forceinline__ void mma_f16(float* d, const unsigned* a, const unsigned* b) {
    asm volatile(
        "mma.sync.aligned.m16n8k16.row.col.f32.f16.f16.f32 "
        "{%0,%1,%2,%3},{%4,%5,%6,%7},{%8,%9},{%0,%1,%2,%3};"
        : "+f"(d[0]), "+f"(d[1]), "+f"(d[2]), "+f"(d[3])
        : "r"(a[0]), "r"(a[1]), "r"(a[2]), "r"(a[3]), "r"(b[0]), "r"(b[1]));
}

#define LDSM_X4(r0, r1, r2, r3, addr) \
    asm volatile("ldmatrix.sync.aligned.m8n8.x4.shared.b16 {%0,%1,%2,%3}, [%4];" \
                 : "=r"(r0), "=r"(r1), "=r"(r2), "=r"(r3) : "r"(addr))

#define LDSM_X4_T(r0, r1, r2, r3, addr) \
    asm volatile("ldmatrix.sync.aligned.m8n8.x4.trans.shared.b16 {%0,%1,%2,%3}, [%4];" \
                 : "=r"(r0), "=r"(r1), "=r"(r2), "=r"(r3) : "r"(addr))

__device__ __forceinline__ void cpasync16(unsigned dst, const void* src) {
    asm volatile("cp.async.cg.shared.global [%0], [%1], 16;" :: "r"(dst), "l"(src));
}
#define CP_COMMIT() asm volatile("cp.async.commit_group;")
#define CP_WAIT(n)  asm volatile("cp.async.wait_group %0;" :: "n"(n))

// ---------------- fp32 -> fp16 convert (with optional scale) -----------------
__global__ void cvt16_kernel(const float* __restrict__ s, __half* __restrict__ d,
                             float scale)
{
    int idx = blockIdx.x * blockDim.x + threadIdx.x;  // exact grid
    float4 v = ((const float4*)s)[idx];
    ((__half2*)d)[2*idx    ] = __floats2half2_rn(v.x * scale, v.y * scale);
    ((__half2*)d)[2*idx + 1] = __floats2half2_rn(v.z * scale, v.w * scale);
}

// ---------------- fp16 GEMM, C[m,n] = sum_k A[m,k]*B[n,k] (NT) ---------------
// 256x128 block tile, BK=32, 256 threads (8 warps: 4 m-slots x 2 n-slots of
// 64x64), cp.async double-buffered smem, ldmatrix fragment loads.
#define WP 20                      // smem pitch in words per 32-half row
#define GA_WORDS (256 * WP)        // A stage words
#define GB_WORDS (128 * WP)        // B stage words
#define GEMM_SMEM_BYTES ((2*GA_WORDS + 2*GB_WORDS) * 4)   // 61440

template<int OUT16>
__global__ void __launch_bounds__(256, 1)
gemm_f16_nt(const __half* __restrict__ A, const __half* __restrict__ Bm,
            void* __restrict__ Cm, int N, int K)
{
    extern __shared__ unsigned gsm[];
    const unsigned smb = (unsigned)__cvta_generic_to_shared(gsm);
    // layout: [A0][A1][B0][B1]
    const unsigned aOff[2] = { smb, smb + GA_WORDS * 4 };
    const unsigned bOff[2] = { smb + 2 * GA_WORDS * 4,
                               smb + 2 * GA_WORDS * 4 + GB_WORDS * 4 };

    const int tid = threadIdx.x;
    const int wid = tid >> 5, lane = tid & 31;
    const int g   = lane >> 2, t4 = lane & 3;
    const int wm  = wid & 3,   wn = wid >> 2;
    const int bm  = blockIdx.y * 256, bn = blockIdx.x * 128;

    const unsigned lrow = (lane & 7) + ((lane >> 3) & 1) * 8;
    const unsigned kofs = (lane >> 4) * 4;

    float acc[4][8][4];
#pragma unroll
    for (int i = 0; i < 4; i++)
#pragma unroll
        for (int j = 0; j < 8; j++)
#pragma unroll
            for (int r = 0; r < 4; r++) acc[i][j][r] = 0.f;

    // ---- cp.async tile issue: A 256 rows, B 128 rows, 4 chunks of 16B each --
#define GEMM_ISSUE(stage, kk)                                                   \
    do {                                                                        \
        _Pragma("unroll")                                                       \
        for (int l = 0; l < 4; l++) {                                           \
            int f = tid + l * 256, row = f >> 2, ch = f & 3;                    \
            cpasync16(aOff[stage] + (unsigned)((row * WP + ch * 4) * 4),        \
                      A + (size_t)(bm + row) * K + (kk) + ch * 8);              \
        }                                                                       \
        _Pragma("unroll")                                                       \
        for (int l = 0; l < 2; l++) {                                           \
            int f = tid + l * 256, row = f >> 2, ch = f & 3;                    \
            cpasync16(bOff[stage] + (unsigned)((row * WP + ch * 4) * 4),        \
                      Bm + (size_t)(bn + row) * K + (kk) + ch * 8);             \
        }                                                                       \
        CP_COMMIT();                                                            \
    } while (0)

    GEMM_ISSUE(0, 0);

    int buf = 0;
    for (int k0 = 0; k0 < K; k0 += 32) {
        const bool has_next = (k0 + 32) < K;
        if (has_next) { GEMM_ISSUE(buf ^ 1, k0 + 32); CP_WAIT(1); }
        else          { CP_WAIT(0); }
        __syncthreads();

#pragma unroll
        for (int ks = 0; ks < 2; ks++) {
            unsigned a[4][4], b[8][2];
#pragma unroll
            for (int mt = 0; mt < 4; mt++) {
                unsigned addr = aOff[buf] +
                    (unsigned)((((unsigned)(wm * 64 + mt * 16) + lrow) * WP
                                + ks * 8 + kofs) * 4);
                LDSM_X4(a[mt][0], a[mt][1], a[mt][2], a[mt][3], addr);
            }
#pragma unroll
            for (int p = 0; p < 4; p++) {
                unsigned addr = bOff[buf] +
                    (unsigned)((((unsigned)(wn * 64 + p * 16) + lrow) * WP
                                + ks * 8 + kofs) * 4);
                LDSM_X4(b[2*p][0], b[2*p+1][0], b[2*p][1], b[2*p+1][1], addr);
            }
#pragma unroll
            for (int mt = 0; mt < 4; mt++)
#pragma unroll
                for (int nt = 0; nt < 8; nt++)
                    mma_f16(acc[mt][nt], a[mt], b[nt]);
        }
        __syncthreads();
        buf ^= 1;
    }

#pragma unroll
    for (int mt = 0; mt < 4; mt++) {
        int r0 = bm + wm * 64 + mt * 16 + g;
#pragma unroll
        for (int nt = 0; nt < 8; nt++) {
            int c = bn + wn * 64 + nt * 8 + 2 * t4;
            if (OUT16) {
                unsigned* o = (unsigned*)Cm;
                o[((size_t)r0 * N + c) >> 1] =
                    packh2(acc[mt][nt][0], acc[mt][nt][1]);
                o[((size_t)(r0 + 8) * N + c) >> 1] =
                    packh2(acc[mt][nt][2], acc[mt][nt][3]);
            } else {
                float* o = (float*)Cm;
                *(float2*)(o + (size_t)r0 * N + c) =
                    make_float2(acc[mt][nt][0], acc[mt][nt][1]);
                *(float2*)(o + (size_t)(r0 + 8) * N + c) =
                    make_float2(acc[mt][nt][2], acc[mt][nt][3]);
            }
        }
    }
}

// ---------------- RoPE (NeoX rotate-half), in place on fp16 ------------------
__global__ void rope_h_kernel(__half* __restrict__ p, const float* __restrict__ freqs,
                              int nh)
{
    int idx = blockIdx.x * blockDim.x + threadIdx.x;
    int pr = idx & 63;
    int h  = (idx >> 6) % nh;
    int bt = idx / (64 * nh);
    int t  = bt & (Tc - 1);
    float c = freqs[(t * 64 + pr) * 2 + 0];
    float s = freqs[(t * 64 + pr) * 2 + 1];
    __half* base = p + ((size_t)bt * nh + h) * Dc;
    float u0 = __half2float(base[pr]);
    float u1 = __half2float(base[pr + 64]);
    base[pr]      = __float2half_rn(u0 * c - u1 * s);
    base[pr + 64] = __float2half_rn(u1 * c + u0 * s);
}

// ---------------- flash attention, fp16 mma, register-resident ---------------
// 128 q-rows per block, 8 warps (16 rows each), 64-row KV tiles.
// cp.async double-buffered K/V tiles; Q A-fragments in registers;
// K via ldmatrix.x4; P C-frag -> A-frag zero-shuffle; V via ldmatrix.x4.trans.
#define KVP 68                         // pitch words per 128-half row (272 B)
#define KST (64 * KVP)                 // words per K (or V) tile
#define ATT_SMEM_BYTES (2 * 2 * KST * 4)   // 69632

__global__ void __launch_bounds__(256, 1)
attn_kernel(const __half* __restrict__ q, const __half* __restrict__ k,
            const __half* __restrict__ v, __half* __restrict__ o)
{
    extern __shared__ unsigned asm_[];
    const unsigned smb = (unsigned)__cvta_generic_to_shared(asm_);

    const int qt = (int)(gridDim.x - 1) - (int)blockIdx.x;  // long blocks first
    const int h = blockIdx.y, b = blockIdx.z;
    const int kvh = h >> 2;
    const int tid = threadIdx.x;
    const int wid = tid >> 5, lane = tid & 31;
    const int g   = lane >> 2, t4 = lane & 3;

    const unsigned lrow = (lane & 7) + ((lane >> 3) & 1) * 8;
    const unsigned kofs = (lane >> 4) * 4;
    const int mat = lane >> 3;
    const unsigned voff = (unsigned)(((mat & 1) * 8 + (lane & 7)) * (KVP * 4)
                                     + (mat >> 1) * 16);

    const int qrow0 = qt * 128 + wid * 16;   // this warp's first q row

    // ---- Q fragments in registers (scale folded into Wq) ----
    unsigned qf[8][4];
    {
        const __half* q0 = q + (((size_t)(b * Tc + qrow0 + g    )) * Hc + h) * Dc;
        const __half* q1 = q0 + (size_t)8 * Hc * Dc;
#pragma unroll
        for (int kb = 0; kb < 8; kb++) {
            qf[kb][0] = *(const unsigned*)(q0 + kb * 16 + 2 * t4);
            qf[kb][1] = *(const unsigned*)(q1 + kb * 16 + 2 * t4);
            qf[kb][2] = *(const unsigned*)(q0 + kb * 16 + 2 * t4 + 8);
            qf[kb][3] = *(const unsigned*)(q1 + kb * 16 + 2 * t4 + 8);
        }
    }

    float accO[16][4];
#pragma unroll
    for (int nt = 0; nt < 16; nt++)
#pragma unroll
        for (int r = 0; r < 4; r++) accO[nt][r] = 0.f;

    float m0 = -1e30f, m1 = -1e30f, l0 = 0.f, l1 = 0.f;

    const __half* kb0 = k + (((size_t)(b * Tc)) * HKVc + kvh) * Dc;
    const __half* vb0 = v + (((size_t)(b * Tc)) * HKVc + kvh) * Dc;

    // issue one K/V tile into stage s via cp.async (all 256 threads)
#define ATT_ISSUE(stage, kt_)                                                   \
    do {                                                                        \
        unsigned kdst = smb + (unsigned)((stage) * 2 * KST * 4);                \
        const __half* gk = kb0 + (size_t)((kt_) * 64) * (HKVc * Dc);            \
        const __half* gv = vb0 + (size_t)((kt_) * 64) * (HKVc * Dc);            \
        _Pragma("unroll")                                                       \
        for (int l = 0; l < 4; l++) {                                           \
            int f = tid + l * 256, row = f >> 4, ch = f & 15;                   \
            unsigned d = (unsigned)((row * KVP + ch * 4) * 4);                  \
            cpasync16(kdst + d,           gk + (size_t)row * (HKVc * Dc) + ch * 8); \
            cpasync16(kdst + KST * 4 + d, gv + (size_t)row * (HKVc * Dc) + ch * 8); \
        }                                                                       \
        CP_COMMIT();                                                            \
    } while (0)

    ATT_ISSUE(0, 0);

    const int nkt = 2 * qt + 2;
    int buf = 0;
    for (int kt = 0; kt < nkt; kt++) {
        const bool has_next = (kt + 1) < nkt;
        if (has_next) { ATT_ISSUE(buf ^ 1, kt + 1); CP_WAIT(1); }
        else          { CP_WAIT(0); }
        __syncthreads();

        if (kt * 64 <= qrow0 + 15) {   // warp has unmasked work in this tile
            const unsigned kbase = smb + (unsigned)(buf * 2 * KST * 4);
            const unsigned vlane = kbase + (unsigned)(KST * 4) + voff;

            // ---- phase A: S(16x64) = Q K^T (K via ldmatrix.x4) ----
            float accS[8][4];
#pragma unroll
            for (int nt = 0; nt < 8; nt++)
#pragma unroll
                for (int r = 0; r < 4; r++) accS[nt][r] = 0.f;

#pragma unroll
            for (int kb = 0; kb < 8; kb++) {
                unsigned bb[8][2];
#pragma unroll
                for (int p = 0; p < 4; p++) {
                    unsigned addr = kbase +
                        (unsigned)((((unsigned)(p * 16) + lrow) * KVP
                                    + kb * 8 + kofs) * 4);
                    LDSM_X4(bb[2*p][0], bb[2*p+1][0], bb[2*p][1], bb[2*p+1][1], addr);
                }
#pragma unroll
                for (int nt = 0; nt < 8; nt++)
                    mma_f16(accS[nt], qf[kb], bb[nt]);
            }

            // ---- causal mask (register) ----
            if (kt * 64 + 63 > qrow0) {
                const int r0 = qrow0 + g, r1 = r0 + 8;
#pragma unroll
                for (int nt = 0; nt < 8; nt++) {
                    int c0 = kt * 64 + nt * 8 + 2 * t4;
                    if (c0     > r0) accS[nt][0] = -1e30f;
                    if (c0 + 1 > r0) accS[nt][1] = -1e30f;
                    if (c0     > r1) accS[nt][2] = -1e30f;
                    if (c0 + 1 > r1) accS[nt][3] = -1e30f;
                }
            }

            // ---- register online softmax (quad = one row pair) ----
            float mt0 = -1e30f, mt1 = -1e30f;
#pragma unroll
            for (int nt = 0; nt < 8; nt++) {
                mt0 = fmaxf(mt0, fmaxf(accS[nt][0], accS[nt][1]));
                mt1 = fmaxf(mt1, fmaxf(accS[nt][2], accS[nt][3]));
            }
            mt0 = fmaxf(mt0, __shfl_xor_sync(0xffffffffu, mt0, 1));
            mt0 = fmaxf(mt0, __shfl_xor_sync(0xffffffffu, mt0, 2));
            mt1 = fmaxf(mt1, __shfl_xor_sync(0xffffffffu, mt1, 1));
            mt1 = fmaxf(mt1, __shfl_xor_sync(0xffffffffu, mt1, 2));
            const float mn0 = fmaxf(m0, mt0), mn1 = fmaxf(m1, mt1);
            const float f0 = __expf(m0 - mn0), f1 = __expf(m1 - mn1);
            m0 = mn0; m1 = mn1;

            float s0 = 0.f, s1 = 0.f;
#pragma unroll
            for (int nt = 0; nt < 8; nt++) {
                accS[nt][0] = __expf(accS[nt][0] - mn0); s0 += accS[nt][0];
                accS[nt][1] = __expf(accS[nt][1] - mn0); s0 += accS[nt][1];
                accS[nt][2] = __expf(accS[nt][2] - mn1); s1 += accS[nt][2];
                accS[nt][3] = __expf(accS[nt][3] - mn1); s1 += accS[nt][3];
            }
            s0 += __shfl_xor_sync(0xffffffffu, s0, 1);
            s0 += __shfl_xor_sync(0xffffffffu, s0, 2);
            s1 += __shfl_xor_sync(0xffffffffu, s1, 1);
            s1 += __shfl_xor_sync(0xffffffffu, s1, 2);
            l0 = l0 * f0 + s0;
            l1 = l1 * f1 + s1;

#pragma unroll
            for (int nt = 0; nt < 16; nt++) {
                accO[nt][0] *= f0; accO[nt][1] *= f0;
                accO[nt][2] *= f1; accO[nt][3] *= f1;
            }

            // ---- phase C: O += P V (zero-shuffle P->A, ldmatrix.trans V) ----
#pragma unroll
            for (int kb = 0; kb < 4; kb++) {
                unsigned pa[4];
                pa[0] = packh2(accS[2*kb  ][0], accS[2*kb  ][1]);
                pa[1] = packh2(accS[2*kb  ][2], accS[2*kb  ][3]);
                pa[2] = packh2(accS[2*kb+1][0], accS[2*kb+1][1]);
                pa[3] = packh2(accS[2*kb+1][2], accS[2*kb+1][3]);
#pragma unroll
                for (int nt2 = 0; nt2 < 8; nt2++) {
                    unsigned r0, r1, r2, r3;
                    unsigned addr = vlane + (unsigned)(kb * 16 * (KVP * 4) + nt2 * 32);
                    LDSM_X4_T(r0, r1, r2, r3, addr);
                    unsigned b0[2] = {r0, r1}, b1[2] = {r2, r3};
                    mma_f16(accO[2*nt2    ], pa, b0);
                    mma_f16(accO[2*nt2 + 1], pa, b1);
                }
            }
        }
        __syncthreads();
        buf ^= 1;
    }

    // ---- epilogue: normalize, convert to fp16, store ----
    const float i0 = 1.f / l0, i1 = 1.f / l1;
    unsigned* go0 = (unsigned*)(o + (((size_t)(b * Tc + qrow0 + g    )) * Hc + h) * Dc);
    unsigned* go1 = (unsigned*)(o + (((size_t)(b * Tc + qrow0 + g + 8)) * Hc + h) * Dc);
#pragma unroll
    for (int nt = 0; nt < 16; nt++) {
        int cw = (nt * 8 + 2 * t4) >> 1;
        go0[cw] = packh2(accO[nt][0] * i0, accO[nt][1] * i0);
        go1[cw] = packh2(accO[nt][2] * i1, accO[nt][3] * i1);
    }
}

// ---------------- host launcher ---------------------------------------------
extern "C" void kernel_launch(void* const* d_in, const int* in_sizes, int n_in,
                              void* d_out, int out_size)
{
    (void)in_sizes; (void)n_in; (void)out_size;
    const float* x     = (const float*)d_in[0];
    const float* freqs = (const float*)d_in[1];
    const float* Wq    = (const float*)d_in[2];
    const float* Wk    = (const float*)d_in[3];
    const float* Wv    = (const float*)d_in[4];
    const float* Wo    = (const float*)d_in[5];
    float* out = (float*)d_out;

    __half *xh, *wqh, *wkh, *wvh, *woh, *qh, *kh, *vh, *aoh;
    cudaGetSymbolAddress((void**)&xh,  g_xh);
    cudaGetSymbolAddress((void**)&wqh, g_wqh);
    cudaGetSymbolAddress((void**)&wkh, g_wkh);
    cudaGetSymbolAddress((void**)&wvh, g_wvh);
    cudaGetSymbolAddress((void**)&woh, g_woh);
    cudaGetSymbolAddress((void**)&qh,  g_qh);
    cudaGetSymbolAddress((void**)&kh,  g_kh);
    cudaGetSymbolAddress((void**)&vh,  g_vh);
    cudaGetSymbolAddress((void**)&aoh, g_aoh);

    cudaFuncSetAttribute(gemm_f16_nt<1>,
                         cudaFuncAttributeMaxDynamicSharedMemorySize,
                         GEMM_SMEM_BYTES);
    cudaFuncSetAttribute(gemm_f16_nt<0>,
                         cudaFuncAttributeMaxDynamicSharedMemorySize,
                         GEMM_SMEM_BYTES);
    cudaFuncSetAttribute(attn_kernel,
                         cudaFuncAttributeMaxDynamicSharedMemorySize,
                         ATT_SMEM_BYTES);

    const float qscale = 0.08838834764831845f;  // 1/sqrt(128)

    // fp32 -> fp16 staging (scale folded into Wq)
    cvt16_kernel<<<((size_t)Mrows*Cc/4)/256, 256>>>(x,  xh,  1.f);
    cvt16_kernel<<<((size_t)Cc*Cc/4)/256,    256>>>(Wq, wqh, qscale);
    cvt16_kernel<<<((size_t)KVC*Cc/4)/256,   256>>>(Wk, wkh, 1.f);
    cvt16_kernel<<<((size_t)KVC*Cc/4)/256,   256>>>(Wv, wvh, 1.f);
    cvt16_kernel<<<((size_t)Cc*Cc/4)/256,    256>>>(Wo, woh, 1.f);

    // projections (fp16 in, fp16 out)
    gemm_f16_nt<1><<<dim3(Cc  / 128, Mrows / 256), 256, GEMM_SMEM_BYTES>>>(xh, wqh, qh, Cc,  Cc);
    gemm_f16_nt<1><<<dim3(KVC / 128, Mrows / 256), 256, GEMM_SMEM_BYTES>>>(xh, wkh, kh, KVC, Cc);
    gemm_f16_nt<1><<<dim3(KVC / 128, Mrows / 256), 256, GEMM_SMEM_BYTES>>>(xh, wvh, vh, KVC, Cc);

    // RoPE (in place, fp16 storage / fp32 math)
    rope_h_kernel<<<(Mrows * Hc   * 64) / 256, 256>>>(qh, freqs, Hc);
    rope_h_kernel<<<(Mrows * HKVc * 64) / 256, 256>>>(kh, freqs, HKVc);

    // causal GQA flash attention (fp16 mma, cp.async pipelined)
    attn_kernel<<<dim3(Tc / 128, Hc, Bc), 256, ATT_SMEM_BYTES>>>(qh, kh, vh, aoh);

    // output projection (fp16 in, fp32 out)
    gemm_f16_nt<0><<<dim3(Cc / 128, Mrows / 256), 256, GEMM_SMEM_BYTES>>>(aoh, woh, out, Cc, Cc);
}

// round 11
// speedup vs baseline: 1.1428x; 1.1428x over previous
#include <cuda_runtime.h>
#include <cuda_fp16.h>
#include <math.h>

#define Bc   4
#define Tc   2048
#define Cc   2048
#define Hc   16
#define HKVc 4
#define Dc   128
#define Mrows (Bc*Tc)          // 8192
#define KVC  (HKVc*Dc)         // 512

// ---------------- scratch (device globals; no runtime allocation) -----------
__device__ __half g_xh [(size_t)Mrows*Cc];
__device__ __half g_wqh[(size_t)Cc*Cc];
__device__ __half g_wkh[(size_t)KVC*Cc];
__device__ __half g_wvh[(size_t)KVC*Cc];
__device__ __half g_woh[(size_t)Cc*Cc];
__device__ __half g_qh [(size_t)Mrows*Cc];   // [b,t,h,d] (Wq pre-scaled by 1/sqrt(d))
__device__ __half g_kh [(size_t)Mrows*KVC];  // [b,t,hkv,d]
__device__ __half g_vh [(size_t)Mrows*KVC];
__device__ __half g_aoh[(size_t)Mrows*Cc];   // attention output

// ---------------- helpers -----------------------------------------------------
__device__ __forceinline__ unsigned packh2(float x, float y) {
    __half2 h = __floats2half2_rn(x, y);
    return *reinterpret_cast<unsigned*>(&h);
}

// D(16x8 fp32) += A(16x16 fp16, row) * B(16x8 fp16, col)
__device__ __forceinline__ void mma_f16(float* d, const unsigned* a, const unsigned* b) {
    asm volatile(
        "mma.sync.aligned.m16n8k16.row.col.f32.f16.f16.f32 "
        "{%0,%1,%2,%3},{%4,%5,%6,%7},{%8,%9},{%0,%1,%2,%3};"
        : "+f"(d[0]), "+f"(d[1]), "+f"(d[2]), "+f"(d[3])
        : "r"(a[0]), "r"(a[1]), "r"(a[2]), "r"(a[3]), "r"(b[0]), "r"(b[1]));
}

#define LDSM_X4(r0, r1, r2, r3, addr) \
    asm volatile("ldmatrix.sync.aligned.m8n8.x4.shared.b16 {%0,%1,%2,%3}, [%4];" \
                 : "=r"(r0), "=r"(r1), "=r"(r2), "=r"(r3) : "r"(addr))

#define LDSM_X4_T(r0, r1, r2, r3, addr) \
    asm volatile("ldmatrix.sync.aligned.m8n8.x4.trans.shared.b16 {%0,%1,%2,%3}, [%4];" \
                 : "=r"(r0), "=r"(r1), "=r"(r2), "=r"(r3) : "r"(addr))

__device__ __forceinline__ void cpasync16(unsigned dst, const void* src) {
    asm volatile("cp.async.cg.shared.global [%0], [%1], 16;" :: "r"(dst), "l"(src));
}
#define CP_COMMIT() asm volatile("cp.async.commit_group;")
#define CP_WAIT(n)  asm volatile("cp.async.wait_group %0;" :: "n"(n))

// ---------------- fp32 -> fp16 convert (with optional scale) -----------------
__global__ void cvt16_kernel(const float* __restrict__ s, __half* __restrict__ d,
                             float scale)
{
    int idx = blockIdx.x * blockDim.x + threadIdx.x;  // exact grid
    float4 v = ((const float4*)s)[idx];
    ((__half2*)d)[2*idx    ] = __floats2half2_rn(v.x * scale, v.y * scale);
    ((__half2*)d)[2*idx + 1] = __floats2half2_rn(v.z * scale, v.w * scale);
}

// ---------------- fp16 GEMM, C[m,n] = sum_k A[m,k]*B[n,k] (NT) ---------------
// PROVEN round-9 config: 128x128 tile, BK=32, 128 threads (4 warps, 2x2 of
// 64x64 warp tiles), 2 CTAs/SM, register-prefetch double-buffered smem.
// Tile row = 32 halfs = 16 words; pitch 20 words.
#define WP 20

template<int OUT16>
__global__ void __launch_bounds__(128, 2)
gemm_f16_nt(const __half* __restrict__ A, const __half* __restrict__ Bm,
            void* __restrict__ Cm, int N, int K)
{
    __shared__ unsigned As[2][128 * WP];
    __shared__ unsigned Bs[2][128 * WP];

    const int tid = threadIdx.x;
    const int wid = tid >> 5, lane = tid & 31;
    const int g   = lane >> 2, t4 = lane & 3;
    const int wm  = wid >> 1,  wn = wid & 1;
    const int bm  = blockIdx.y * 128, bn = blockIdx.x * 128;

    float acc[4][8][4];
#pragma unroll
    for (int i = 0; i < 4; i++)
#pragma unroll
        for (int j = 0; j < 8; j++)
#pragma unroll
            for (int r = 0; r < 4; r++) acc[i][j][r] = 0.f;

    uint4 va[4], vb[4];

    // prologue: tile k0=0
#pragma unroll
    for (int l = 0; l < 4; l++) {
        int f = tid + l * 128, row = f >> 2, ch = f & 3;
        va[l] = *(const uint4*)(A  + (size_t)(bm + row) * K + ch * 8);
        vb[l] = *(const uint4*)(Bm + (size_t)(bn + row) * K + ch * 8);
    }
#pragma unroll
    for (int l = 0; l < 4; l++) {
        int f = tid + l * 128, row = f >> 2, ch = f & 3;
        *(uint4*)&As[0][row * WP + ch * 4] = va[l];
        *(uint4*)&Bs[0][row * WP + ch * 4] = vb[l];
    }
    __syncthreads();

    int buf = 0;
    for (int k0 = 0; k0 < K; k0 += 32) {
        const bool has_next = (k0 + 32) < K;
        if (has_next) {
#pragma unroll
            for (int l = 0; l < 4; l++) {
                int f = tid + l * 128, row = f >> 2, ch = f & 3;
                va[l] = *(const uint4*)(A  + (size_t)(bm + row) * K + k0 + 32 + ch * 8);
                vb[l] = *(const uint4*)(Bm + (size_t)(bn + row) * K + k0 + 32 + ch * 8);
            }
        }

#pragma unroll
        for (int ks = 0; ks < 2; ks++) {
            unsigned a[4][4], b[8][2];
#pragma unroll
            for (int mt = 0; mt < 4; mt++) {
                int m = wm * 64 + mt * 16;
                a[mt][0] = As[buf][(m + g    ) * WP + ks * 8 + t4];
                a[mt][1] = As[buf][(m + g + 8) * WP + ks * 8 + t4];
                a[mt][2] = As[buf][(m + g    ) * WP + ks * 8 + t4 + 4];
                a[mt][3] = As[buf][(m + g + 8) * WP + ks * 8 + t4 + 4];
            }
#pragma unroll
            for (int nt = 0; nt < 8; nt++) {
                int n = wn * 64 + nt * 8;
                b[nt][0] = Bs[buf][(n + g) * WP + ks * 8 + t4];
                b[nt][1] = Bs[buf][(n + g) * WP + ks * 8 + t4 + 4];
            }
#pragma unroll
            for (int mt = 0; mt < 4; mt++)
#pragma unroll
                for (int nt = 0; nt < 8; nt++)
                    mma_f16(acc[mt][nt], a[mt], b[nt]);
        }

        if (has_next) {
#pragma unroll
            for (int l = 0; l < 4; l++) {
                int f = tid + l * 128, row = f >> 2, ch = f & 3;
                *(uint4*)&As[buf ^ 1][row * WP + ch * 4] = va[l];
                *(uint4*)&Bs[buf ^ 1][row * WP + ch * 4] = vb[l];
            }
        }
        __syncthreads();
        buf ^= 1;
    }

#pragma unroll
    for (int mt = 0; mt < 4; mt++) {
        int r0 = bm + wm * 64 + mt * 16 + g;
#pragma unroll
        for (int nt = 0; nt < 8; nt++) {
            int c = bn + wn * 64 + nt * 8 + 2 * t4;
            if (OUT16) {
                unsigned* o = (unsigned*)Cm;
                o[((size_t)r0 * N + c) >> 1] =
                    packh2(acc[mt][nt][0], acc[mt][nt][1]);
                o[((size_t)(r0 + 8) * N + c) >> 1] =
                    packh2(acc[mt][nt][2], acc[mt][nt][3]);
            } else {
                float* o = (float*)Cm;
                *(float2*)(o + (size_t)r0 * N + c) =
                    make_float2(acc[mt][nt][0], acc[mt][nt][1]);
                *(float2*)(o + (size_t)(r0 + 8) * N + c) =
                    make_float2(acc[mt][nt][2], acc[mt][nt][3]);
            }
        }
    }
}

// ---------------- RoPE (NeoX rotate-half), in place on fp16 ------------------
__global__ void rope_h_kernel(__half* __restrict__ p, const float* __restrict__ freqs,
                              int nh)
{
    int idx = blockIdx.x * blockDim.x + threadIdx.x;
    int pr = idx & 63;
    int h  = (idx >> 6) % nh;
    int bt = idx / (64 * nh);
    int t  = bt & (Tc - 1);
    float c = freqs[(t * 64 + pr) * 2 + 0];
    float s = freqs[(t * 64 + pr) * 2 + 1];
    __half* base = p + ((size_t)bt * nh + h) * Dc;
    float u0 = __half2float(base[pr]);
    float u1 = __half2float(base[pr + 64]);
    base[pr]      = __float2half_rn(u0 * c - u1 * s);
    base[pr + 64] = __float2half_rn(u1 * c + u0 * s);
}

// ---------------- flash attention, fp16 mma, register-resident ---------------
// Round-10 version (proven correct): 128 q-rows per block, 8 warps, 64-row KV
// tiles, cp.async double-buffered K/V, K via ldmatrix.x4, V via ldmatrix.x4
// .trans, zero-shuffle P->A, long-diagonal blocks scheduled first.
#define KVP 68                         // pitch words per 128-half row (272 B)
#define KST (64 * KVP)                 // words per K (or V) tile
#define ATT_SMEM_BYTES (2 * 2 * KST * 4)   // 69632

__global__ void __launch_bounds__(256, 1)
attn_kernel(const __half* __restrict__ q, const __half* __restrict__ k,
            const __half* __restrict__ v, __half* __restrict__ o)
{
    extern __shared__ unsigned asm_[];
    const unsigned smb = (unsigned)__cvta_generic_to_shared(asm_);

    const int qt = (int)(gridDim.x - 1) - (int)blockIdx.x;  // long blocks first
    const int h = blockIdx.y, b = blockIdx.z;
    const int kvh = h >> 2;
    const int tid = threadIdx.x;
    const int wid = tid >> 5, lane = tid & 31;
    const int g   = lane >> 2, t4 = lane & 3;

    const unsigned lrow = (lane & 7) + ((lane >> 3) & 1) * 8;
    const unsigned kofs = (lane >> 4) * 4;
    const int mat = lane >> 3;
    const unsigned voff = (unsigned)(((mat & 1) * 8 + (lane & 7)) * (KVP * 4)
                                     + (mat >> 1) * 16);

    const int qrow0 = qt * 128 + wid * 16;   // this warp's first q row

    // ---- Q fragments in registers (scale folded into Wq) ----
    unsigned qf[8][4];
    {
        const __half* q0 = q + (((size_t)(b * Tc + qrow0 + g    )) * Hc + h) * Dc;
        const __half* q1 = q0 + (size_t)8 * Hc * Dc;
#pragma unroll
        for (int kb = 0; kb < 8; kb++) {
            qf[kb][0] = *(const unsigned*)(q0 + kb * 16 + 2 * t4);
            qf[kb][1] = *(const unsigned*)(q1 + kb * 16 + 2 * t4);
            qf[kb][2] = *(const unsigned*)(q0 + kb * 16 + 2 * t4 + 8);
            qf[kb][3] = *(const unsigned*)(q1 + kb * 16 + 2 * t4 + 8);
        }
    }

    float accO[16][4];
#pragma unroll
    for (int nt = 0; nt < 16; nt++)
#pragma unroll
        for (int r = 0; r < 4; r++) accO[nt][r] = 0.f;

    float m0 = -1e30f, m1 = -1e30f, l0 = 0.f, l1 = 0.f;

    const __half* kb0 = k + (((size_t)(b * Tc)) * HKVc + kvh) * Dc;
    const __half* vb0 = v + (((size_t)(b * Tc)) * HKVc + kvh) * Dc;

    // issue one K/V tile into stage s via cp.async (all 256 threads)
#define ATT_ISSUE(stage, kt_)                                                   \
    do {                                                                        \
        unsigned kdst = smb + (unsigned)((stage) * 2 * KST * 4);                \
        const __half* gk = kb0 + (size_t)((kt_) * 64) * (HKVc * Dc);            \
        const __half* gv = vb0 + (size_t)((kt_) * 64) * (HKVc * Dc);            \
        _Pragma("unroll")                                                       \
        for (int l = 0; l < 4; l++) {                                           \
            int f = tid + l * 256, row = f >> 4, ch = f & 15;                   \
            unsigned d = (unsigned)((row * KVP + ch * 4) * 4);                  \
            cpasync16(kdst + d,           gk + (size_t)row * (HKVc * Dc) + ch * 8); \
            cpasync16(kdst + KST * 4 + d, gv + (size_t)row * (HKVc * Dc) + ch * 8); \
        }                                                                       \
        CP_COMMIT();                                                            \
    } while (0)

    ATT_ISSUE(0, 0);

    const int nkt = 2 * qt + 2;
    int buf = 0;
    for (int kt = 0; kt < nkt; kt++) {
        const bool has_next = (kt + 1) < nkt;
        if (has_next) { ATT_ISSUE(buf ^ 1, kt + 1); CP_WAIT(1); }
        else          { CP_WAIT(0); }
        __syncthreads();

        if (kt * 64 <= qrow0 + 15) {   // warp has unmasked work in this tile
            const unsigned kbase = smb + (unsigned)(buf * 2 * KST * 4);
            const unsigned vlane = kbase + (unsigned)(KST * 4) + voff;

            // ---- phase A: S(16x64) = Q K^T (K via ldmatrix.x4) ----
            float accS[8][4];
#pragma unroll
            for (int nt = 0; nt < 8; nt++)
#pragma unroll
                for (int r = 0; r < 4; r++) accS[nt][r] = 0.f;

#pragma unroll
            for (int kb = 0; kb < 8; kb++) {
                unsigned bb[8][2];
#pragma unroll
                for (int p = 0; p < 4; p++) {
                    unsigned addr = kbase +
                        (unsigned)((((unsigned)(p * 16) + lrow) * KVP
                                    + kb * 8 + kofs) * 4);
                    LDSM_X4(bb[2*p][0], bb[2*p+1][0], bb[2*p][1], bb[2*p+1][1], addr);
                }
#pragma unroll
                for (int nt = 0; nt < 8; nt++)
                    mma_f16(accS[nt], qf[kb], bb[nt]);
            }

            // ---- causal mask (register) ----
            if (kt * 64 + 63 > qrow0) {
                const int r0 = qrow0 + g, r1 = r0 + 8;
#pragma unroll
                for (int nt = 0; nt < 8; nt++) {
                    int c0 = kt * 64 + nt * 8 + 2 * t4;
                    if (c0     > r0) accS[nt][0] = -1e30f;
                    if (c0 + 1 > r0) accS[nt][1] = -1e30f;
                    if (c0     > r1) accS[nt][2] = -1e30f;
                    if (c0 + 1 > r1) accS[nt][3] = -1e30f;
                }
            }

            // ---- register online softmax (quad = one row pair) ----
            float mt0 = -1e30f, mt1 = -1e30f;
#pragma unroll
            for (int nt = 0; nt < 8; nt++) {
                mt0 = fmaxf(mt0, fmaxf(accS[nt][0], accS[nt][1]));
                mt1 = fmaxf(mt1, fmaxf(accS[nt][2], accS[nt][3]));
            }
            mt0 = fmaxf(mt0, __shfl_xor_sync(0xffffffffu, mt0, 1));
            mt0 = fmaxf(mt0, __shfl_xor_sync(0xffffffffu, mt0, 2));
            mt1 = fmaxf(mt1, __shfl_xor_sync(0xffffffffu, mt1, 1));
            mt1 = fmaxf(mt1, __shfl_xor_sync(0xffffffffu, mt1, 2));
            const float mn0 = fmaxf(m0, mt0), mn1 = fmaxf(m1, mt1);
            const float f0 = __expf(m0 - mn0), f1 = __expf(m1 - mn1);
            m0 = mn0; m1 = mn1;

            float s0 = 0.f, s1 = 0.f;
#pragma unroll
            for (int nt = 0; nt < 8; nt++) {
                accS[nt][0] = __expf(accS[nt][0] - mn0); s0 += accS[nt][0];
                accS[nt][1] = __expf(accS[nt][1] - mn0); s0 += accS[nt][1];
                accS[nt][2] = __expf(accS[nt][2] - mn1); s1 += accS[nt][2];
                accS[nt][3] = __expf(accS[nt][3] - mn1); s1 += accS[nt][3];
            }
            s0 += __shfl_xor_sync(0xffffffffu, s0, 1);
            s0 += __shfl_xor_sync(0xffffffffu, s0, 2);
            s1 += __shfl_xor_sync(0xffffffffu, s1, 1);
            s1 += __shfl_xor_sync(0xffffffffu, s1, 2);
            l0 = l0 * f0 + s0;
            l1 = l1 * f1 + s1;

#pragma unroll
            for (int nt = 0; nt < 16; nt++) {
                accO[nt][0] *= f0; accO[nt][1] *= f0;
                accO[nt][2] *= f1; accO[nt][3] *= f1;
            }

            // ---- phase C: O += P V (zero-shuffle P->A, ldmatrix.trans V) ----
#pragma unroll
            for (int kb = 0; kb < 4; kb++) {
                unsigned pa[4];
                pa[0] = packh2(accS[2*kb  ][0], accS[2*kb  ][1]);
                pa[1] = packh2(accS[2*kb  ][2], accS[2*kb  ][3]);
                pa[2] = packh2(accS[2*kb+1][0], accS[2*kb+1][1]);
                pa[3] = packh2(accS[2*kb+1][2], accS[2*kb+1][3]);
#pragma unroll
                for (int nt2 = 0; nt2 < 8; nt2++) {
                    unsigned r0, r1, r2, r3;
                    unsigned addr = vlane + (unsigned)(kb * 16 * (KVP * 4) + nt2 * 32);
                    LDSM_X4_T(r0, r1, r2, r3, addr);
                    unsigned b0[2] = {r0, r1}, b1[2] = {r2, r3};
                    mma_f16(accO[2*nt2    ], pa, b0);
                    mma_f16(accO[2*nt2 + 1], pa, b1);
                }
            }
        }
        __syncthreads();
        buf ^= 1;
    }

    // ---- epilogue: normalize, convert to fp16, store ----
    const float i0 = 1.f / l0, i1 = 1.f / l1;
    unsigned* go0 = (unsigned*)(o + (((size_t)(b * Tc + qrow0 + g    )) * Hc + h) * Dc);
    unsigned* go1 = (unsigned*)(o + (((size_t)(b * Tc + qrow0 + g + 8)) * Hc + h) * Dc);
#pragma unroll
    for (int nt = 0; nt < 16; nt++) {
        int cw = (nt * 8 + 2 * t4) >> 1;
        go0[cw] = packh2(accO[nt][0] * i0, accO[nt][1] * i0);
        go1[cw] = packh2(accO[nt][2] * i1, accO[nt][3] * i1);
    }
}

// ---------------- host launcher ---------------------------------------------
extern "C" void kernel_launch(void* const* d_in, const int* in_sizes, int n_in,
                              void* d_out, int out_size)
{
    (void)in_sizes; (void)n_in; (void)out_size;
    const float* x     = (const float*)d_in[0];
    const float* freqs = (const float*)d_in[1];
    const float* Wq    = (const float*)d_in[2];
    const float* Wk    = (const float*)d_in[3];
    const float* Wv    = (const float*)d_in[4];
    const float* Wo    = (const float*)d_in[5];
    float* out = (float*)d_out;

    __half *xh, *wqh, *wkh, *wvh, *woh, *qh, *kh, *vh, *aoh;
    cudaGetSymbolAddress((void**)&xh,  g_xh);
    cudaGetSymbolAddress((void**)&wqh, g_wqh);
    cudaGetSymbolAddress((void**)&wkh, g_wkh);
    cudaGetSymbolAddress((void**)&wvh, g_wvh);
    cudaGetSymbolAddress((void**)&woh, g_woh);
    cudaGetSymbolAddress((void**)&qh,  g_qh);
    cudaGetSymbolAddress((void**)&kh,  g_kh);
    cudaGetSymbolAddress((void**)&vh,  g_vh);
    cudaGetSymbolAddress((void**)&aoh, g_aoh);

    cudaFuncSetAttribute(attn_kernel,
                         cudaFuncAttributeMaxDynamicSharedMemorySize,
                         ATT_SMEM_BYTES);

    const float qscale = 0.08838834764831845f;  // 1/sqrt(128)

    // fp32 -> fp16 staging (scale folded into Wq)
    cvt16_kernel<<<((size_t)Mrows*Cc/4)/256, 256>>>(x,  xh,  1.f);
    cvt16_kernel<<<((size_t)Cc*Cc/4)/256,    256>>>(Wq, wqh, qscale);
    cvt16_kernel<<<((size_t)KVC*Cc/4)/256,   256>>>(Wk, wkh, 1.f);
    cvt16_kernel<<<((size_t)KVC*Cc/4)/256,   256>>>(Wv, wvh, 1.f);
    cvt16_kernel<<<((size_t)Cc*Cc/4)/256,    256>>>(Wo, woh, 1.f);

    // projections (fp16 in, fp16 out) — proven round-9 GEMM config
    gemm_f16_nt<1><<<dim3(Cc  / 128, Mrows / 128), 128>>>(xh, wqh, qh, Cc,  Cc);
    gemm_f16_nt<1><<<dim3(KVC / 128, Mrows / 128), 128>>>(xh, wkh, kh, KVC, Cc);
    gemm_f16_nt<1><<<dim3(KVC / 128, Mrows / 128), 128>>>(xh, wvh, vh, KVC, Cc);

    // RoPE (in place, fp16 storage / fp32 math)
    rope_h_kernel<<<(Mrows * Hc   * 64) / 256, 256>>>(qh, freqs, Hc);
    rope_h_kernel<<<(Mrows * HKVc * 64) / 256, 256>>>(kh, freqs, HKVc);

    // causal GQA flash attention (fp16 mma, cp.async pipelined)
    attn_kernel<<<dim3(Tc / 128, Hc, Bc), 256, ATT_SMEM_BYTES>>>(qh, kh, vh, aoh);

    // output projection (fp16 in, fp32 out)
    gemm_f16_nt<0><<<dim3(Cc / 128, Mrows / 128), 128>>>(aoh, woh, out, Cc, Cc);
}

// round 13
// speedup vs baseline: 1.1684x; 1.0224x over previous
#include <cuda_runtime.h>
#include <cuda_fp16.h>
#include <math.h>

#define Bc   4
#define Tc   2048
#define Cc   2048
#define Hc   16
#define HKVc 4
#define Dc   128
#define Mrows (Bc*Tc)          // 8192
#define KVC  (HKVc*Dc)         // 512
#define QKVS (Cc + 2*KVC)      // 3072: fused qkv row stride
#define KOFF Cc                // 2048: k column offset in fused buffer
#define VOFF (Cc + KVC)        // 2560: v column offset

// ---------------- scratch (device globals; no runtime allocation) -----------
__device__ __half g_xh  [(size_t)Mrows*Cc];
__device__ __half g_wqkv[(size_t)QKVS*Cc];    // [Wq(scaled); Wk; Wv]
__device__ __half g_woh [(size_t)Cc*Cc];
__device__ __half g_qkv [(size_t)Mrows*QKVS]; // [b,t][q(16x128) k(4x128) v(4x128)]
__device__ __half g_aoh [(size_t)Mrows*Cc];   // attention output [b,t,h,d]

// ---------------- helpers -----------------------------------------------------
__device__ __forceinline__ unsigned packh2(float x, float y) {
    __half2 h = __floats2half2_rn(x, y);
    return *reinterpret_cast<unsigned*>(&h);
}

// D(16x8 fp32) += A(16x16 fp16, row) * B(16x8 fp16, col)
__device__ __forceinline__ void mma_f16(float* d, const unsigned* a, const unsigned* b) {
    asm volatile(
        "mma.sync.aligned.m16n8k16.row.col.f32.f16.f16.f32 "
        "{%0,%1,%2,%3},{%4,%5,%6,%7},{%8,%9},{%0,%1,%2,%3};"
        : "+f"(d[0]), "+f"(d[1]), "+f"(d[2]), "+f"(d[3])
        : "r"(a[0]), "r"(a[1]), "r"(a[2]), "r"(a[3]), "r"(b[0]), "r"(b[1]));
}

#define LDSM_X4(r0, r1, r2, r3, addr) \
    asm volatile("ldmatrix.sync.aligned.m8n8.x4.shared.b16 {%0,%1,%2,%3}, [%4];" \
                 : "=r"(r0), "=r"(r1), "=r"(r2), "=r"(r3) : "r"(addr))

#define LDSM_X4_T(r0, r1, r2, r3, addr) \
    asm volatile("ldmatrix.sync.aligned.m8n8.x4.trans.shared.b16 {%0,%1,%2,%3}, [%4];" \
                 : "=r"(r0), "=r"(r1), "=r"(r2), "=r"(r3) : "r"(addr))

__device__ __forceinline__ void cpasync16(unsigned dst, const void* src) {
    asm volatile("cp.async.cg.shared.global [%0], [%1], 16;" :: "r"(dst), "l"(src));
}
#define CP_COMMIT() asm volatile("cp.async.commit_group;")
#define CP_WAIT(n)  asm volatile("cp.async.wait_group %0;" :: "n"(n))

// ---------------- fp32 -> fp16 convert (with optional scale) -----------------
__global__ void cvt16_kernel(const float* __restrict__ s, __half* __restrict__ d,
                             float scale)
{
    int idx = blockIdx.x * blockDim.x + threadIdx.x;  // exact grid
    float4 v = ((const float4*)s)[idx];
    ((__half2*)d)[2*idx    ] = __floats2half2_rn(v.x * scale, v.y * scale);
    ((__half2*)d)[2*idx + 1] = __floats2half2_rn(v.z * scale, v.w * scale);
}

// ---------------- fp16 GEMM, C[m,n] = sum_k A[m,k]*B[n,k] (NT) ---------------
// Proven 128x128 tile / BK=32 / 128 threads / 2 CTAs/SM / register-prefetch
// double buffer; fragment loads upgraded to ldmatrix.x4 (proven in round 10).
#define WP 20   // smem pitch in 32-bit words per 32-half row

template<int OUT16>
__global__ void __launch_bounds__(128, 2)
gemm_f16_nt(const __half* __restrict__ A, const __half* __restrict__ Bm,
            void* __restrict__ Cm, int N, int K)
{
    __shared__ unsigned As[2][128 * WP];
    __shared__ unsigned Bs[2][128 * WP];

    const int tid = threadIdx.x;
    const int wid = tid >> 5, lane = tid & 31;
    const int g   = lane >> 2, t4 = lane & 3;
    const int wm  = wid >> 1,  wn = wid & 1;
    const int bm  = blockIdx.y * 128, bn = blockIdx.x * 128;

    const unsigned aBase = (unsigned)__cvta_generic_to_shared(As);
    const unsigned bBase = (unsigned)__cvta_generic_to_shared(Bs);
    const unsigned lrow = (lane & 7) + ((lane >> 3) & 1) * 8;
    const unsigned kofs = (lane >> 4) * 4;

    float acc[4][8][4];
#pragma unroll
    for (int i = 0; i < 4; i++)
#pragma unroll
        for (int j = 0; j < 8; j++)
#pragma unroll
            for (int r = 0; r < 4; r++) acc[i][j][r] = 0.f;

    uint4 va[4], vb[4];

    // prologue: tile k0=0
#pragma unroll
    for (int l = 0; l < 4; l++) {
        int f = tid + l * 128, row = f >> 2, ch = f & 3;
        va[l] = *(const uint4*)(A  + (size_t)(bm + row) * K + ch * 8);
        vb[l] = *(const uint4*)(Bm + (size_t)(bn + row) * K + ch * 8);
    }
#pragma unroll
    for (int l = 0; l < 4; l++) {
        int f = tid + l * 128, row = f >> 2, ch = f & 3;
        *(uint4*)&As[0][row * WP + ch * 4] = va[l];
        *(uint4*)&Bs[0][row * WP + ch * 4] = vb[l];
    }
    __syncthreads();

    int buf = 0;
    for (int k0 = 0; k0 < K; k0 += 32) {
        const bool has_next = (k0 + 32) < K;
        if (has_next) {
#pragma unroll
            for (int l = 0; l < 4; l++) {
                int f = tid + l * 128, row = f >> 2, ch = f & 3;
                va[l] = *(const uint4*)(A  + (size_t)(bm + row) * K + k0 + 32 + ch * 8);
                vb[l] = *(const uint4*)(Bm + (size_t)(bn + row) * K + k0 + 32 + ch * 8);
            }
        }

        const unsigned aB = aBase + (unsigned)(buf * 128 * WP * 4);
        const unsigned bB = bBase + (unsigned)(buf * 128 * WP * 4);
#pragma unroll
        for (int ks = 0; ks < 2; ks++) {
            unsigned a[4][4], b[8][2];
#pragma unroll
            for (int mt = 0; mt < 4; mt++) {
                unsigned addr = aB +
                    (unsigned)((((unsigned)(wm * 64 + mt * 16) + lrow) * WP
                                + ks * 8 + kofs) * 4);
                LDSM_X4(a[mt][0], a[mt][1], a[mt][2], a[mt][3], addr);
            }
#pragma unroll
            for (int p = 0; p < 4; p++) {
                unsigned addr = bB +
                    (unsigned)((((unsigned)(wn * 64 + p * 16) + lrow) * WP
                                + ks * 8 + kofs) * 4);
                LDSM_X4(b[2*p][0], b[2*p+1][0], b[2*p][1], b[2*p+1][1], addr);
            }
#pragma unroll
            for (int mt = 0; mt < 4; mt++)
#pragma unroll
                for (int nt = 0; nt < 8; nt++)
                    mma_f16(acc[mt][nt], a[mt], b[nt]);
        }

        if (has_next) {
#pragma unroll
            for (int l = 0; l < 4; l++) {
                int f = tid + l * 128, row = f >> 2, ch = f & 3;
                *(uint4*)&As[buf ^ 1][row * WP + ch * 4] = va[l];
                *(uint4*)&Bs[buf ^ 1][row * WP + ch * 4] = vb[l];
            }
        }
        __syncthreads();
        buf ^= 1;
    }

#pragma unroll
    for (int mt = 0; mt < 4; mt++) {
        int r0 = bm + wm * 64 + mt * 16 + g;
#pragma unroll
        for (int nt = 0; nt < 8; nt++) {
            int c = bn + wn * 64 + nt * 8 + 2 * t4;
            if (OUT16) {
                unsigned* o = (unsigned*)Cm;
                o[((size_t)r0 * N + c) >> 1] =
                    packh2(acc[mt][nt][0], acc[mt][nt][1]);
                o[((size_t)(r0 + 8) * N + c) >> 1] =
                    packh2(acc[mt][nt][2], acc[mt][nt][3]);
            } else {
                float* o = (float*)Cm;
                *(float2*)(o + (size_t)r0 * N + c) =
                    make_float2(acc[mt][nt][0], acc[mt][nt][1]);
                *(float2*)(o + (size_t)(r0 + 8) * N + c) =
                    make_float2(acc[mt][nt][2], acc[mt][nt][3]);
            }
        }
    }
}

// ---------------- RoPE (NeoX rotate-half), in place on fp16 ------------------
// base = p + bt*rowstride + coloff + h*Dc
__global__ void rope_h_kernel(__half* __restrict__ p, const float* __restrict__ freqs,
                              int nh, int rowstride, int coloff)
{
    int idx = blockIdx.x * blockDim.x + threadIdx.x;
    int pr = idx & 63;
    int h  = (idx >> 6) % nh;
    int bt = idx / (64 * nh);
    int t  = bt & (Tc - 1);
    float c = freqs[(t * 64 + pr) * 2 + 0];
    float s = freqs[(t * 64 + pr) * 2 + 1];
    __half* base = p + (size_t)bt * rowstride + coloff + h * Dc;
    float u0 = __half2float(base[pr]);
    float u1 = __half2float(base[pr + 64]);
    base[pr]      = __float2half_rn(u0 * c - u1 * s);
    base[pr + 64] = __float2half_rn(u1 * c + u0 * s);
}

// ---------------- flash attention, fp16 mma, register-resident ---------------
// Round-11 structure; Q/K/V read from the fused QKV buffer (stride 3072).
#define KVP 68                         // pitch words per 128-half row (272 B)
#define KST (64 * KVP)                 // words per K (or V) tile
#define ATT_SMEM_BYTES (2 * 2 * KST * 4)   // 69632

__global__ void __launch_bounds__(256, 1)
attn_kernel(const __half* __restrict__ qkv, __half* __restrict__ o)
{
    extern __shared__ unsigned asm_[];
    const unsigned smb = (unsigned)__cvta_generic_to_shared(asm_);

    const int qt = (int)(gridDim.x - 1) - (int)blockIdx.x;  // long blocks first
    const int h = blockIdx.y, b = blockIdx.z;
    const int kvh = h >> 2;
    const int tid = threadIdx.x;
    const int wid = tid >> 5, lane = tid & 31;
    const int g   = lane >> 2, t4 = lane & 3;

    const unsigned lrow = (lane & 7) + ((lane >> 3) & 1) * 8;
    const unsigned kofs = (lane >> 4) * 4;
    const int mat = lane >> 3;
    const unsigned voff = (unsigned)(((mat & 1) * 8 + (lane & 7)) * (KVP * 4)
                                     + (mat >> 1) * 16);

    const int qrow0 = qt * 128 + wid * 16;   // this warp's first q row

    // ---- Q fragments in registers (scale folded into Wq) ----
    unsigned qf[8][4];
    {
        const __half* q0 = qkv + (size_t)(b * Tc + qrow0 + g) * QKVS + h * Dc;
        const __half* q1 = q0 + (size_t)8 * QKVS;
#pragma unroll
        for (int kb = 0; kb < 8; kb++) {
            qf[kb][0] = *(const unsigned*)(q0 + kb * 16 + 2 * t4);
            qf[kb][1] = *(const unsigned*)(q1 + kb * 16 + 2 * t4);
            qf[kb][2] = *(const unsigned*)(q0 + kb * 16 + 2 * t4 + 8);
            qf[kb][3] = *(const unsigned*)(q1 + kb * 16 + 2 * t4 + 8);
        }
    }

    float accO[16][4];
#pragma unroll
    for (int nt = 0; nt < 16; nt++)
#pragma unroll
        for (int r = 0; r < 4; r++) accO[nt][r] = 0.f;

    float m0 = -1e30f, m1 = -1e30f, l0 = 0.f, l1 = 0.f;

    const __half* kb0 = qkv + (size_t)(b * Tc) * QKVS + KOFF + kvh * Dc;
    const __half* vb0 = qkv + (size_t)(b * Tc) * QKVS + VOFF + kvh * Dc;

#define ATT_ISSUE(stage, kt_)                                                   \
    do {                                                                        \
        unsigned kdst = smb + (unsigned)((stage) * 2 * KST * 4);                \
        const __half* gk = kb0 + (size_t)((kt_) * 64) * QKVS;                   \
        const __half* gv = vb0 + (size_t)((kt_) * 64) * QKVS;                   \
        _Pragma("unroll")                                                       \
        for (int l = 0; l < 4; l++) {                                           \
            int f = tid + l * 256, row = f >> 4, ch = f & 15;                   \
            unsigned d = (unsigned)((row * KVP + ch * 4) * 4);                  \
            cpasync16(kdst + d,           gk + (size_t)row * QKVS + ch * 8);    \
            cpasync16(kdst + KST * 4 + d, gv + (size_t)row * QKVS + ch * 8);    \
        }                                                                       \
        CP_COMMIT();                                                            \
    } while (0)

    ATT_ISSUE(0, 0);

    const int nkt = 2 * qt + 2;
    int buf = 0;
    for (int kt = 0; kt < nkt; kt++) {
        const bool has_next = (kt + 1) < nkt;
        if (has_next) { ATT_ISSUE(buf ^ 1, kt + 1); CP_WAIT(1); }
        else          { CP_WAIT(0); }
        __syncthreads();

        if (kt * 64 <= qrow0 + 15) {   // warp has unmasked work in this tile
            const unsigned kbase = smb + (unsigned)(buf * 2 * KST * 4);
            const unsigned vlane = kbase + (unsigned)(KST * 4) + voff;

            // ---- phase A: S(16x64) = Q K^T (K via ldmatrix.x4) ----
            float accS[8][4];
#pragma unroll
            for (int nt = 0; nt < 8; nt++)
#pragma unroll
                for (int r = 0; r < 4; r++) accS[nt][r] = 0.f;

#pragma unroll
            for (int kb = 0; kb < 8; kb++) {
                unsigned bb[8][2];
#pragma unroll
                for (int p = 0; p < 4; p++) {
                    unsigned addr = kbase +
                        (unsigned)((((unsigned)(p * 16) + lrow) * KVP
                                    + kb * 8 + kofs) * 4);
                    LDSM_X4(bb[2*p][0], bb[2*p+1][0], bb[2*p][1], bb[2*p+1][1], addr);
                }
#pragma unroll
                for (int nt = 0; nt < 8; nt++)
                    mma_f16(accS[nt], qf[kb], bb[nt]);
            }

            // ---- causal mask (register) ----
            if (kt * 64 + 63 > qrow0) {
                const int r0 = qrow0 + g, r1 = r0 + 8;
#pragma unroll
                for (int nt = 0; nt < 8; nt++) {
                    int c0 = kt * 64 + nt * 8 + 2 * t4;
                    if (c0     > r0) accS[nt][0] = -1e30f;
                    if (c0 + 1 > r0) accS[nt][1] = -1e30f;
                    if (c0     > r1) accS[nt][2] = -1e30f;
                    if (c0 + 1 > r1) accS[nt][3] = -1e30f;
                }
            }

            // ---- register online softmax (quad = one row pair) ----
            float mt0 = -1e30f, mt1 = -1e30f;
#pragma unroll
            for (int nt = 0; nt < 8; nt++) {
                mt0 = fmaxf(mt0, fmaxf(accS[nt][0], accS[nt][1]));
                mt1 = fmaxf(mt1, fmaxf(accS[nt][2], accS[nt][3]));
            }
            mt0 = fmaxf(mt0, __shfl_xor_sync(0xffffffffu, mt0, 1));
            mt0 = fmaxf(mt0, __shfl_xor_sync(0xffffffffu, mt0, 2));
            mt1 = fmaxf(mt1, __shfl_xor_sync(0xffffffffu, mt1, 1));
            mt1 = fmaxf(mt1, __shfl_xor_sync(0xffffffffu, mt1, 2));
            const float mn0 = fmaxf(m0, mt0), mn1 = fmaxf(m1, mt1);
            const float f0 = __expf(m0 - mn0), f1 = __expf(m1 - mn1);
            m0 = mn0; m1 = mn1;

            float s0 = 0.f, s1 = 0.f;
#pragma unroll
            for (int nt = 0; nt < 8; nt++) {
                accS[nt][0] = __expf(accS[nt][0] - mn0); s0 += accS[nt][0];
                accS[nt][1] = __expf(accS[nt][1] - mn0); s0 += accS[nt][1];
                accS[nt][2] = __expf(accS[nt][2] - mn1); s1 += accS[nt][2];
                accS[nt][3] = __expf(accS[nt][3] - mn1); s1 += accS[nt][3];
            }
            s0 += __shfl_xor_sync(0xffffffffu, s0, 1);
            s0 += __shfl_xor_sync(0xffffffffu, s0, 2);
            s1 += __shfl_xor_sync(0xffffffffu, s1, 1);
            s1 += __shfl_xor_sync(0xffffffffu, s1, 2);
            l0 = l0 * f0 + s0;
            l1 = l1 * f1 + s1;

#pragma unroll
            for (int nt = 0; nt < 16; nt++) {
                accO[nt][0] *= f0; accO[nt][1] *= f0;
                accO[nt][2] *= f1; accO[nt][3] *= f1;
            }

            // ---- phase C: O += P V (zero-shuffle P->A, ldmatrix.trans V) ----
#pragma unroll
            for (int kb = 0; kb < 4; kb++) {
                unsigned pa[4];
                pa[0] = packh2(accS[2*kb  ][0], accS[2*kb  ][1]);
                pa[1] = packh2(accS[2*kb  ][2], accS[2*kb  ][3]);
                pa[2] = packh2(accS[2*kb+1][0], accS[2*kb+1][1]);
                pa[3] = packh2(accS[2*kb+1][2], accS[2*kb+1][3]);
#pragma unroll
                for (int nt2 = 0; nt2 < 8; nt2++) {
                    unsigned r0, r1, r2, r3;
                    unsigned addr = vlane + (unsigned)(kb * 16 * (KVP * 4) + nt2 * 32);
                    LDSM_X4_T(r0, r1, r2, r3, addr);
                    unsigned b0[2] = {r0, r1}, b1[2] = {r2, r3};
                    mma_f16(accO[2*nt2    ], pa, b0);
                    mma_f16(accO[2*nt2 + 1], pa, b1);
                }
            }
        }
        __syncthreads();
        buf ^= 1;
    }

    // ---- epilogue: normalize, convert to fp16, store ----
    const float i0 = 1.f / l0, i1 = 1.f / l1;
    unsigned* go0 = (unsigned*)(o + (((size_t)(b * Tc + qrow0 + g    )) * Hc + h) * Dc);
    unsigned* go1 = (unsigned*)(o + (((size_t)(b * Tc + qrow0 + g + 8)) * Hc + h) * Dc);
#pragma unroll
    for (int nt = 0; nt < 16; nt++) {
        int cw = (nt * 8 + 2 * t4) >> 1;
        go0[cw] = packh2(accO[nt][0] * i0, accO[nt][1] * i0);
        go1[cw] = packh2(accO[nt][2] * i1, accO[nt][3] * i1);
    }
#undef ATT_ISSUE
}

// ---------------- host launcher ---------------------------------------------
extern "C" void kernel_launch(void* const* d_in, const int* in_sizes, int n_in,
                              void* d_out, int out_size)
{
    (void)in_sizes; (void)n_in; (void)out_size;
    const float* x     = (const float*)d_in[0];
    const float* freqs = (const float*)d_in[1];
    const float* Wq    = (const float*)d_in[2];
    const float* Wk    = (const float*)d_in[3];
    const float* Wv    = (const float*)d_in[4];
    const float* Wo    = (const float*)d_in[5];
    float* out = (float*)d_out;

    __half *xh, *wqkv, *woh, *qkv, *aoh;
    cudaGetSymbolAddress((void**)&xh,   g_xh);
    cudaGetSymbolAddress((void**)&wqkv, g_wqkv);
    cudaGetSymbolAddress((void**)&woh,  g_woh);
    cudaGetSymbolAddress((void**)&qkv,  g_qkv);
    cudaGetSymbolAddress((void**)&aoh,  g_aoh);

    cudaFuncSetAttribute(attn_kernel,
                         cudaFuncAttributeMaxDynamicSharedMemorySize,
                         ATT_SMEM_BYTES);

    const float qscale = 0.08838834764831845f;  // 1/sqrt(128)

    // fp32 -> fp16 staging: x, fused [Wq(scaled); Wk; Wv], Wo
    cvt16_kernel<<<((size_t)Mrows*Cc/4)/256, 256>>>(x,  xh, 1.f);
    cvt16_kernel<<<((size_t)Cc*Cc/4)/256,    256>>>(Wq, wqkv,                    qscale);
    cvt16_kernel<<<((size_t)KVC*Cc/4)/256,   256>>>(Wk, wqkv + (size_t)KOFF*Cc,  1.f);
    cvt16_kernel<<<((size_t)KVC*Cc/4)/256,   256>>>(Wv, wqkv + (size_t)VOFF*Cc,  1.f);
    cvt16_kernel<<<((size_t)Cc*Cc/4)/256,    256>>>(Wo, woh, 1.f);

    // fused QKV projection (fp16 in, fp16 out): [8192,3072] = x @ [Wq;Wk;Wv]^T
    gemm_f16_nt<1><<<dim3(QKVS / 128, Mrows / 128), 128>>>(xh, wqkv, qkv, QKVS, Cc);

    // RoPE (in place on fused buffer)
    rope_h_kernel<<<(Mrows * Hc   * 64) / 256, 256>>>(qkv, freqs, Hc,   QKVS, 0);
    rope_h_kernel<<<(Mrows * HKVc * 64) / 256, 256>>>(qkv, freqs, HKVc, QKVS, KOFF);

    // causal GQA flash attention (fp16 mma, cp.async pipelined)
    attn_kernel<<<dim3(Tc / 128, Hc, Bc), 256, ATT_SMEM_BYTES>>>(qkv, aoh);

    // output projection (fp16 in, fp32 out)
    gemm_f16_nt<0><<<dim3(Cc / 128, Mrows / 128), 128>>>(aoh, woh, out, Cc, Cc);
}